// round 16
// baseline (speedup 1.0000x reference)
#include <cuda_runtime.h>
#include <cuda_fp16.h>
#include <cstdint>
#include <math.h>

// ---------------------------------------------------------------------------
// Problem constants
// ---------------------------------------------------------------------------
#define T_TOK   4096
#define H_DIM   2048
#define E_NUM   32
#define I_DIM   1024
#define IS_DIM  2048
#define TOPK    8
#define NGRP    8
#define TOPKG   4

#define NT_MAX   288             // 32768/128 + 32 experts of pad tiles
#define ROWS_MAX (NT_MAX * 128)  // 36864

// GEMM tile config (fp16 mma.sync path)
#define BK     32                // K per tile (halves)
#define SROW   40                // smem row stride in halves (80B; ldmatrix conflict-free)
#define STG    (256 * SROW)      // halves per pipeline stage (A:128 rows + B:128 rows)
#define NSTAGE 5                 // 5 stages, 2 ktiles consumed per barrier

// ---------------------------------------------------------------------------
// Device scratch
// ---------------------------------------------------------------------------
__device__ float         g_Wdense[T_TOK * E_NUM];
__device__ unsigned char g_Slot[T_TOK * E_NUM];
__device__ int           g_counts[E_NUM];
__device__ int           g_tile_e[NT_MAX];
__device__ int           g_rtok[ROWS_MAX];
__device__ float         g_rw[ROWS_MAX];
__device__ unsigned char g_rslot[ROWS_MAX];

// fp16-preconverted operands
__device__ __half g_Xh[(size_t)T_TOK * H_DIM];
__device__ __half g_W1h[(size_t)E_NUM * I_DIM * H_DIM];
__device__ __half g_W3h[(size_t)E_NUM * I_DIM * H_DIM];
__device__ __half g_W2h[(size_t)E_NUM * H_DIM * I_DIM];
__device__ __half g_SW1h[(size_t)IS_DIM * H_DIM];
__device__ __half g_SW3h[(size_t)IS_DIM * H_DIM];
__device__ __half g_SW2h[(size_t)H_DIM * IS_DIM];

__device__ __half g_Hbh[(size_t)ROWS_MAX * I_DIM];   // routed intermediate
__device__ __half g_Hsh[(size_t)T_TOK * IS_DIM];     // shared intermediate
__device__ float  g_Y[(size_t)T_TOK * TOPK * H_DIM]; // per-slot routed outputs

// ---------------------------------------------------------------------------
// Helpers
// ---------------------------------------------------------------------------
__device__ __forceinline__ void mma_f16(float* c, const unsigned* a, const unsigned* b) {
    asm volatile(
        "mma.sync.aligned.m16n8k16.row.col.f32.f16.f16.f32 "
        "{%0,%1,%2,%3}, {%4,%5,%6,%7}, {%8,%9}, {%0,%1,%2,%3};\n"
        : "+f"(c[0]), "+f"(c[1]), "+f"(c[2]), "+f"(c[3])
        : "r"(a[0]), "r"(a[1]), "r"(a[2]), "r"(a[3]), "r"(b[0]), "r"(b[1]));
}

__device__ __forceinline__ void ldsm4(unsigned* r, const void* p) {
    unsigned a = (unsigned)__cvta_generic_to_shared(p);
    asm volatile("ldmatrix.sync.aligned.m8n8.x4.shared.b16 {%0,%1,%2,%3}, [%4];\n"
                 : "=r"(r[0]), "=r"(r[1]), "=r"(r[2]), "=r"(r[3]) : "r"(a));
}

__device__ __forceinline__ void cp16(void* sptr, const void* gptr) {
    unsigned sa = (unsigned)__cvta_generic_to_shared(sptr);
    asm volatile("cp.async.cg.shared.global [%0], [%1], 16;\n" :: "r"(sa), "l"(gptr));
}
#define CP_COMMIT() asm volatile("cp.async.commit_group;\n")
#define CP_WAIT1()  asm volatile("cp.async.wait_group 1;\n")

__device__ __forceinline__ float silu_f(float x) { return x / (1.f + __expf(-x)); }

// ---------------------------------------------------------------------------
// merged fp32->fp16 conversion for ALL operands (one launch) + counts clear
// ---------------------------------------------------------------------------
#define N8_X   (T_TOK * H_DIM / 8)
#define N8_W   (E_NUM * I_DIM * H_DIM / 8)
#define N8_SW  (IS_DIM * H_DIM / 8)
#define N8_TOT (N8_X + 3 * N8_W + 3 * N8_SW)

__device__ __forceinline__ void cv8(const float4* in, uint4* out, int i) {
    float4 v0 = in[2 * i];
    float4 v1 = in[2 * i + 1];
    __half2 h[4];
    h[0] = __floats2half2_rn(v0.x, v0.y);
    h[1] = __floats2half2_rn(v0.z, v0.w);
    h[2] = __floats2half2_rn(v1.x, v1.y);
    h[3] = __floats2half2_rn(v1.z, v1.w);
    out[i] = *reinterpret_cast<uint4*>(h);
}

__global__ void k_cvtall(const float4* __restrict__ x,
                         const float4* __restrict__ w1, const float4* __restrict__ w3,
                         const float4* __restrict__ w2, const float4* __restrict__ sw1,
                         const float4* __restrict__ sw3, const float4* __restrict__ sw2) {
    int i = blockIdx.x * blockDim.x + threadIdx.x;
    if (i < E_NUM) g_counts[i] = 0;
    if (i >= N8_TOT) return;
    if (i < N8_X) { cv8(x, (uint4*)g_Xh, i); return; }
    i -= N8_X;
    if (i < N8_W) { cv8(w1, (uint4*)g_W1h, i); return; }
    i -= N8_W;
    if (i < N8_W) { cv8(w3, (uint4*)g_W3h, i); return; }
    i -= N8_W;
    if (i < N8_W) { cv8(w2, (uint4*)g_W2h, i); return; }
    i -= N8_W;
    if (i < N8_SW) { cv8(sw1, (uint4*)g_SW1h, i); return; }
    i -= N8_SW;
    if (i < N8_SW) { cv8(sw3, (uint4*)g_SW3h, i); return; }
    i -= N8_SW;
    cv8(sw2, (uint4*)g_SW2h, i);
}

// ---------------------------------------------------------------------------
// 1) router (one warp per token) — writes full dense rows
// ---------------------------------------------------------------------------
__global__ void __launch_bounds__(128) k_router(const float* __restrict__ X,
                                                const float* __restrict__ GW,
                                                const float* __restrict__ EB) {
    const int warp = threadIdx.x >> 5;
    const int lane = threadIdx.x & 31;
    const int t = blockIdx.x * 4 + warp;

    __shared__ float ssw[4][32];
    __shared__ float ssc[4][32];
    __shared__ float sout[4][32];
    __shared__ unsigned char sslot[4][32];

    const float* x = X + (size_t)t * H_DIM;
    const float* g = GW + (size_t)lane * H_DIM;
    float a0=0.f,a1=0.f,a2=0.f,a3=0.f,a4=0.f,a5=0.f,a6=0.f,a7=0.f;
    for (int k = 0; k < H_DIM; k += 8) {
        float4 xv0 = *(const float4*)(x + k);
        float4 gv0 = *(const float4*)(g + k);
        float4 xv1 = *(const float4*)(x + k + 4);
        float4 gv1 = *(const float4*)(g + k + 4);
        a0 += xv0.x * gv0.x;  a1 += xv0.y * gv0.y;
        a2 += xv0.z * gv0.z;  a3 += xv0.w * gv0.w;
        a4 += xv1.x * gv1.x;  a5 += xv1.y * gv1.y;
        a6 += xv1.z * gv1.z;  a7 += xv1.w * gv1.w;
    }
    float logit = ((a0 + a4) + (a1 + a5)) + ((a2 + a6) + (a3 + a7));

    double scd = 1.0 / (1.0 + exp(-(double)logit));
    float sc = (float)scd;
    float sw = sc + EB[lane];
    ssw[warp][lane] = sw;
    ssc[warp][lane] = sc;
    sout[warp][lane] = 0.f;
    sslot[warp][lane] = 0;
    __syncwarp();

    if (lane == 0) {
        const float* swp = ssw[warp];
        const float* scp = ssc[warp];
        float gsc[NGRP];
#pragma unroll
        for (int gg = 0; gg < NGRP; gg++) {
            float m1 = -1e30f, m2 = -1e30f;
#pragma unroll
            for (int j = 0; j < 4; j++) {
                float v = swp[gg * 4 + j];
                if (v > m1) { m2 = m1; m1 = v; }
                else if (v > m2) m2 = v;
            }
            gsc[gg] = m1 + m2;
        }
        unsigned gmask = 0;
        for (int it = 0; it < TOPKG; it++) {
            int bg = 0; float bv = -1e30f;
            for (int gg = 0; gg < NGRP; gg++)
                if (!((gmask >> gg) & 1) && gsc[gg] > bv) { bv = gsc[gg]; bg = gg; }
            gmask |= 1u << bg;
        }
        int idx[TOPK]; float wsel[TOPK]; float wsum = 0.f;
        unsigned taken = 0;
        for (int it = 0; it < TOPK; it++) {
            int be = 0; float bv = -1e30f;
            for (int ee = 0; ee < E_NUM; ee++) {
                if (!((gmask >> (ee >> 2)) & 1)) continue;
                if ((taken >> ee) & 1) continue;
                if (swp[ee] > bv) { bv = swp[ee]; be = ee; }
            }
            taken |= 1u << be;
            idx[it] = be;
            wsel[it] = scp[be];
            wsum += scp[be];
        }
        float inv = 2.5f / (wsum + 1e-20f);
        for (int it = 0; it < TOPK; it++) {
            int ee = idx[it];
            sout[warp][ee] = wsel[it] * inv;
            sslot[warp][ee] = (unsigned char)it;
            atomicAdd(&g_counts[ee], 1);
        }
    }
    __syncwarp();
    g_Wdense[(size_t)t * E_NUM + lane] = sout[warp][lane];
    g_Slot[(size_t)t * E_NUM + lane]   = sslot[warp][lane];
}

// ---------------------------------------------------------------------------
// 2) scatter (folds offsets/tile-map/pad-init): one block per expert
// ---------------------------------------------------------------------------
__global__ void __launch_bounds__(1024) k_scatter() {
    const int e = blockIdx.x;
    const int tid = threadIdx.x;

    __shared__ int soff[E_NUM], spad[E_NUM];
    if (tid < 32) {
        int c = g_counts[tid];
        int p = (c + 127) & ~127;
        int incl = p;
#pragma unroll
        for (int d = 1; d < 32; d <<= 1) {
            int v = __shfl_up_sync(0xFFFFFFFFu, incl, d);
            if (tid >= d) incl += v;
        }
        soff[tid] = incl - p;
        spad[tid] = p;
    }
    __syncthreads();

    if (e == 0) {
        for (int tt = tid; tt < NT_MAX; tt += blockDim.x) {
            int owner = -1;
            int r = tt << 7;
#pragma unroll
            for (int ee = 0; ee < E_NUM; ee++)
                if (r >= soff[ee] && r < soff[ee] + spad[ee]) owner = ee;
            g_tile_e[tt] = owner;
        }
    }
    {
        int base = soff[e] + g_counts[e];
        int end  = soff[e] + spad[e];
        for (int i = base + tid; i < end; i += blockDim.x) {
            g_rtok[i] = -1;
            g_rw[i] = 0.f;
            g_rslot[i] = 0;
        }
    }

    const int base_t = tid * 4;
    float w[4]; int cnt = 0;
#pragma unroll
    for (int i = 0; i < 4; i++) {
        w[i] = g_Wdense[(size_t)(base_t + i) * E_NUM + e];
        cnt += (w[i] != 0.f);
    }
    const int lane = tid & 31, wid = tid >> 5;
    int incl = cnt;
#pragma unroll
    for (int d = 1; d < 32; d <<= 1) {
        int v = __shfl_up_sync(0xFFFFFFFFu, incl, d);
        if (lane >= d) incl += v;
    }
    __shared__ int wsum[32];
    if (lane == 31) wsum[wid] = incl;
    __syncthreads();
    if (wid == 0) {
        int v = wsum[lane];
#pragma unroll
        for (int d = 1; d < 32; d <<= 1) {
            int u = __shfl_up_sync(0xFFFFFFFFu, v, d);
            if (lane >= d) v += u;
        }
        wsum[lane] = v;
    }
    __syncthreads();
    int excl = incl - cnt + (wid ? wsum[wid - 1] : 0);
    int pos = soff[e] + excl;
#pragma unroll
    for (int i = 0; i < 4; i++) {
        if (w[i] != 0.f) {
            g_rtok[pos] = base_t + i;
            g_rw[pos] = w[i];
            g_rslot[pos] = g_Slot[(size_t)(base_t + i) * E_NUM + e];
            pos++;
        }
    }
}

// ---------------------------------------------------------------------------
// 4) up GEMM (fp16): H = silu(A W1^T) * (A W3^T). CTA 128x64 dual, 256 thr,
//    8 warps (4m x 2n), warp 32x32, m16n8k16, 5-stage cp.async, 2 CTAs/SM.
//    ONE barrier per TWO ktiles.
// ---------------------------------------------------------------------------
__global__ void __launch_bounds__(256, 2) k_up(const __half* __restrict__ W1b,
                                               const __half* __restrict__ W3b,
                                               int K, int N, int routed) {
    extern __shared__ __half smh[];
    const int bx = blockIdx.x, by = blockIdx.y;
    int e = 0;
    if (routed) { e = g_tile_e[by]; if (e < 0) return; }
    const size_t wstride = (size_t)N * K;
    const __half* W1 = W1b + (size_t)e * wstride;
    const __half* W3 = W3b + (size_t)e * wstride;
    __half* Hout = routed ? g_Hbh : g_Hsh;

    const int tid = threadIdx.x;
    const int lane = tid & 31;
    const int warp = tid >> 5;
    const int wm = (warp >> 1) << 5;   // 0,32,64,96
    const int wn = (warp & 1) << 5;    // 0,32

    const __half* apg[2]; int sAo[2];
#pragma unroll
    for (int i = 0; i < 2; i++) {
        int c = tid + 256 * i;
        int r = c >> 2, colh = (c & 3) << 3;
        int grow = (by << 7) + r;
        int tok = routed ? g_rtok[grow] : grow;
        if (tok < 0) tok = 0;
        apg[i] = g_Xh + (size_t)tok * K + colh;
        sAo[i] = r * SROW + colh;
    }
    const __half *b1g, *b3g; int sBo;
    {
        int r = tid >> 2, colh = (tid & 3) << 3;
        b1g = W1 + (size_t)((bx << 6) + r) * K + colh;
        b3g = W3 + (size_t)((bx << 6) + r) * K + colh;
        sBo = r * SROW + colh;
    }

    float cg[2][4][4], cu[2][4][4];
#pragma unroll
    for (int mi = 0; mi < 2; mi++)
#pragma unroll
        for (int ni = 0; ni < 4; ni++)
#pragma unroll
            for (int q = 0; q < 4; q++) { cg[mi][ni][q] = 0.f; cu[mi][ni][q] = 0.f; }

    const int NT = K >> 5;   // BK=32; always even

#define UP_FETCH(KT) do {                                         \
        __half* s_ = smh + ((KT) % NSTAGE) * STG;                 \
        int off_ = (KT) << 5;                                     \
        cp16(s_ + sAo[0], apg[0] + off_);                         \
        cp16(s_ + sAo[1], apg[1] + off_);                         \
        cp16(s_ + 128 * SROW + sBo, b1g + off_);                  \
        cp16(s_ + 192 * SROW + sBo, b3g + off_);                  \
    } while (0)

    // one tile of compute: hoisted ldsm for both kk halves, then all MMAs
    auto do_tile = [&](int t) {
        const __half* As  = smh + (t % NSTAGE) * STG;
        const __half* B1s = As + 128 * SROW;
        const __half* B3s = As + 192 * SROW;
        unsigned a[2][2][4], b1[2][4][2], b3[2][4][2];
#pragma unroll
        for (int kk = 0; kk < 2; kk++) {
            const int kb = kk << 4;
            {
                const __half* p = As + (size_t)(wm + (lane & 15)) * SROW
                                   + kb + ((lane >> 4) << 3);
                ldsm4(a[kk][0], p);
                ldsm4(a[kk][1], p + 16 * SROW);
            }
            {
                int row = ((lane >> 4) << 3) + (lane & 7);
                int col = kb + (((lane >> 3) & 1) << 3);
                unsigned t0[4], t1[4];
                const __half* p = B1s + (size_t)(wn + row) * SROW + col;
                ldsm4(t0, p);
                ldsm4(t1, p + 16 * SROW);
                b1[kk][0][0]=t0[0]; b1[kk][0][1]=t0[1]; b1[kk][1][0]=t0[2]; b1[kk][1][1]=t0[3];
                b1[kk][2][0]=t1[0]; b1[kk][2][1]=t1[1]; b1[kk][3][0]=t1[2]; b1[kk][3][1]=t1[3];
                const __half* q = B3s + (size_t)(wn + row) * SROW + col;
                ldsm4(t0, q);
                ldsm4(t1, q + 16 * SROW);
                b3[kk][0][0]=t0[0]; b3[kk][0][1]=t0[1]; b3[kk][1][0]=t0[2]; b3[kk][1][1]=t0[3];
                b3[kk][2][0]=t1[0]; b3[kk][2][1]=t1[1]; b3[kk][3][0]=t1[2]; b3[kk][3][1]=t1[3];
            }
        }
#pragma unroll
        for (int kk = 0; kk < 2; kk++)
#pragma unroll
            for (int mi = 0; mi < 2; mi++)
#pragma unroll
                for (int ni = 0; ni < 4; ni++) {
                    mma_f16(cg[mi][ni], a[kk][mi], b1[kk][ni]);
                    mma_f16(cu[mi][ni], a[kk][mi], b3[kk][ni]);
                }
    };

    UP_FETCH(0); CP_COMMIT();
    UP_FETCH(1); CP_COMMIT();
    UP_FETCH(2); CP_COMMIT();

    for (int kt = 0; kt < NT; kt += 2) {
        CP_WAIT1();              // tiles kt, kt+1 resident (tile kt+2 may be in flight)
        __syncthreads();
        if (kt + 3 < NT) UP_FETCH(kt + 3);
        CP_COMMIT();
        if (kt + 4 < NT) UP_FETCH(kt + 4);
        CP_COMMIT();
        do_tile(kt);
        do_tile(kt + 1);
    }
#undef UP_FETCH

    const int lr = lane >> 2, lc2 = (lane & 3) << 1;
#pragma unroll
    for (int mi = 0; mi < 2; mi++)
#pragma unroll
        for (int ni = 0; ni < 4; ni++)
#pragma unroll
            for (int h = 0; h < 2; h++) {
                int row = (by << 7) + wm + mi * 16 + lr + h * 8;
                int col = (bx << 6) + wn + ni * 8 + lc2;
                float g0 = cg[mi][ni][h * 2], g1 = cg[mi][ni][h * 2 + 1];
                float u0 = cu[mi][ni][h * 2], u1 = cu[mi][ni][h * 2 + 1];
                __half2 hv = __floats2half2_rn(silu_f(g0) * u0, silu_f(g1) * u1);
                *reinterpret_cast<__half2*>(&Hout[(size_t)row * N + col]) = hv;
            }
}

// ---------------------------------------------------------------------------
// 5) down GEMM (fp16): Y = H W2^T. CTA 128x128, 256 thr, 8 warps (2m x 4n),
//    warp 64x32; same 5-stage / 2-ktiles-per-barrier structure.
// ---------------------------------------------------------------------------
__global__ void __launch_bounds__(256, 2) k_down(const __half* __restrict__ W2b,
                                                 int K, int routed,
                                                 float* __restrict__ Outp) {
    extern __shared__ __half smh[];
    const int bx = blockIdx.x, by = blockIdx.y;
    const int N = H_DIM;
    int e = 0;
    if (routed) { e = g_tile_e[by]; if (e < 0) return; }
    const __half* W2 = W2b + (size_t)e * N * K;
    const __half* Ain = routed ? g_Hbh : g_Hsh;

    const int tid = threadIdx.x;
    const int lane = tid & 31;
    const int warp = tid >> 5;
    const int wm = (warp >> 2) << 6;   // 0,64
    const int wn = (warp & 3) << 5;    // 0,32,64,96

    const __half *apg[2], *bpg[2]; int sLo[2];
#pragma unroll
    for (int i = 0; i < 2; i++) {
        int c = tid + 256 * i;
        int r = c >> 2, colh = (c & 3) << 3;
        apg[i] = Ain + (size_t)((by << 7) + r) * K + colh;
        bpg[i] = W2 + (size_t)((bx << 7) + r) * K + colh;
        sLo[i] = r * SROW + colh;
    }

    float cc[4][4][4];
#pragma unroll
    for (int mi = 0; mi < 4; mi++)
#pragma unroll
        for (int ni = 0; ni < 4; ni++)
#pragma unroll
            for (int q = 0; q < 4; q++) cc[mi][ni][q] = 0.f;

    const int NT = K >> 5;

#define DN_FETCH(KT) do {                                         \
        __half* s_ = smh + ((KT) % NSTAGE) * STG;                 \
        int off_ = (KT) << 5;                                     \
        cp16(s_ + sLo[0], apg[0] + off_);                         \
        cp16(s_ + sLo[1], apg[1] + off_);                         \
        cp16(s_ + 128 * SROW + sLo[0], bpg[0] + off_);            \
        cp16(s_ + 128 * SROW + sLo[1], bpg[1] + off_);            \
    } while (0)

    auto do_tile = [&](int t) {
        const __half* As = smh + (t % NSTAGE) * STG;
        const __half* Bs = As + 128 * SROW;
        unsigned a[2][4][4], b[2][4][2];
#pragma unroll
        for (int kk = 0; kk < 2; kk++) {
            const int kb = kk << 4;
            {
                const __half* p = As + (size_t)(wm + (lane & 15)) * SROW
                                   + kb + ((lane >> 4) << 3);
#pragma unroll
                for (int mi = 0; mi < 4; mi++)
                    ldsm4(a[kk][mi], p + mi * 16 * SROW);
            }
            {
                int row = ((lane >> 4) << 3) + (lane & 7);
                int col = kb + (((lane >> 3) & 1) << 3);
                unsigned t0[4], t1[4];
                const __half* p = Bs + (size_t)(wn + row) * SROW + col;
                ldsm4(t0, p);
                ldsm4(t1, p + 16 * SROW);
                b[kk][0][0]=t0[0]; b[kk][0][1]=t0[1]; b[kk][1][0]=t0[2]; b[kk][1][1]=t0[3];
                b[kk][2][0]=t1[0]; b[kk][2][1]=t1[1]; b[kk][3][0]=t1[2]; b[kk][3][1]=t1[3];
            }
        }
#pragma unroll
        for (int kk = 0; kk < 2; kk++)
#pragma unroll
            for (int mi = 0; mi < 4; mi++)
#pragma unroll
                for (int ni = 0; ni < 4; ni++)
                    mma_f16(cc[mi][ni], a[kk][mi], b[kk][ni]);
    };

    DN_FETCH(0); CP_COMMIT();
    DN_FETCH(1); CP_COMMIT();
    DN_FETCH(2); CP_COMMIT();

    for (int kt = 0; kt < NT; kt += 2) {
        CP_WAIT1();
        __syncthreads();
        if (kt + 3 < NT) DN_FETCH(kt + 3);
        CP_COMMIT();
        if (kt + 4 < NT) DN_FETCH(kt + 4);
        CP_COMMIT();
        do_tile(kt);
        do_tile(kt + 1);
    }
#undef DN_FETCH

    const int lr = lane >> 2, lc2 = (lane & 3) << 1;
#pragma unroll
    for (int mi = 0; mi < 4; mi++)
#pragma unroll
        for (int h = 0; h < 2; h++) {
            int row = (by << 7) + wm + mi * 16 + lr + h * 8;
            if (routed) {
                int tok = g_rtok[row];
                if (tok < 0) continue;
                float w = g_rw[row];
                int slot = g_rslot[row];
                float* yrow = &g_Y[((size_t)tok * TOPK + slot) * H_DIM];
#pragma unroll
                for (int ni = 0; ni < 4; ni++) {
                    int col = (bx << 7) + wn + ni * 8 + lc2;
                    float2 v;
                    v.x = w * cc[mi][ni][h * 2];
                    v.y = w * cc[mi][ni][h * 2 + 1];
                    *reinterpret_cast<float2*>(&yrow[col]) = v;
                }
            } else {
                float* orow = &Outp[(size_t)row * H_DIM];
#pragma unroll
                for (int ni = 0; ni < 4; ni++) {
                    int col = (bx << 7) + wn + ni * 8 + lc2;
                    float2 v;
                    v.x = cc[mi][ni][h * 2];
                    v.y = cc[mi][ni][h * 2 + 1];
                    *reinterpret_cast<float2*>(&orow[col]) = v;
                }
            }
        }
}

// ---------------------------------------------------------------------------
// 6) combine: out += sum over 8 routed slots
// ---------------------------------------------------------------------------
__global__ void k_combine(float* __restrict__ out) {
    int i = blockIdx.x * blockDim.x + threadIdx.x;
    const float4* Y4 = reinterpret_cast<const float4*>(g_Y);
    float4* O4 = reinterpret_cast<float4*>(out);
    int t = i >> 9;
    int c = i & 511;
    float4 acc = O4[i];
    const float4* yb = Y4 + ((size_t)t * TOPK) * 512 + c;
#pragma unroll
    for (int s = 0; s < TOPK; s++) {
        float4 v = yb[(size_t)s * 512];
        acc.x += v.x; acc.y += v.y; acc.z += v.z; acc.w += v.w;
    }
    O4[i] = acc;
}

// ---------------------------------------------------------------------------
// Launch
// ---------------------------------------------------------------------------
extern "C" void kernel_launch(void* const* d_in, const int* in_sizes, int n_in,
                              void* d_out, int out_size) {
    const float* hs  = (const float*)d_in[0];
    const float* gw  = (const float*)d_in[1];
    const float* eb  = (const float*)d_in[2];
    const float* w1  = (const float*)d_in[3];
    const float* w3  = (const float*)d_in[4];
    const float* w2  = (const float*)d_in[5];
    const float* sw1 = (const float*)d_in[6];
    const float* sw3 = (const float*)d_in[7];
    const float* sw2 = (const float*)d_in[8];
    float* out = (float*)d_out;

    static __half* p_W1h = nullptr;
    if (!p_W1h) {
        cudaGetSymbolAddress((void**)&p_W1h, g_W1h);
        cudaFuncSetAttribute((const void*)k_up,
                             cudaFuncAttributeMaxDynamicSharedMemorySize,
                             NSTAGE * STG * (int)sizeof(__half));
        cudaFuncSetAttribute((const void*)k_down,
                             cudaFuncAttributeMaxDynamicSharedMemorySize,
                             NSTAGE * STG * (int)sizeof(__half));
    }
    static __half *p_W3h = nullptr, *p_W2h = nullptr, *p_SW1h = nullptr,
                  *p_SW3h = nullptr, *p_SW2h = nullptr;
    if (!p_W3h) {
        cudaGetSymbolAddress((void**)&p_W3h,  g_W3h);
        cudaGetSymbolAddress((void**)&p_W2h,  g_W2h);
        cudaGetSymbolAddress((void**)&p_SW1h, g_SW1h);
        cudaGetSymbolAddress((void**)&p_SW3h, g_SW3h);
        cudaGetSymbolAddress((void**)&p_SW2h, g_SW2h);
    }

    // 0) merged fp32->fp16 conversion (also zeroes g_counts)
    k_cvtall<<<(N8_TOT + 255) / 256, 256>>>(
        (const float4*)hs, (const float4*)w1, (const float4*)w3, (const float4*)w2,
        (const float4*)sw1, (const float4*)sw3, (const float4*)sw2);

    // 1) routing
    k_router<<<T_TOK / 4, 128>>>(hs, gw, eb);
    k_scatter<<<E_NUM, 1024>>>();

    const int smem = NSTAGE * STG * (int)sizeof(__half);

    // routed experts
    k_up<<<dim3(I_DIM / 64, NT_MAX), 256, smem>>>(p_W1h, p_W3h, H_DIM, I_DIM, 1);
    k_down<<<dim3(H_DIM / 128, NT_MAX), 256, smem>>>(p_W2h, I_DIM, 1, nullptr);

    // shared expert (writes d_out directly)
    k_up<<<dim3(IS_DIM / 64, T_TOK / 128), 256, smem>>>(p_SW1h, p_SW3h, H_DIM, IS_DIM, 0);
    k_down<<<dim3(H_DIM / 128, T_TOK / 128), 256, smem>>>(p_SW2h, IS_DIM, 0, out);

    // final combine
    k_combine<<<(T_TOK * H_DIM / 4) / 256, 256>>>(out);

    (void)in_sizes; (void)n_in; (void)out_size;
}

// round 17
// speedup vs baseline: 1.1187x; 1.1187x over previous
#include <cuda_runtime.h>
#include <cuda_fp16.h>
#include <cstdint>
#include <math.h>

// ---------------------------------------------------------------------------
// Problem constants
// ---------------------------------------------------------------------------
#define T_TOK   4096
#define H_DIM   2048
#define E_NUM   32
#define I_DIM   1024
#define IS_DIM  2048
#define TOPK    8
#define NGRP    8
#define TOPKG   4

#define NT_MAX   288             // 32768/128 + 32 experts of pad tiles
#define ROWS_MAX (NT_MAX * 128)  // 36864

// GEMM tile config (fp16 mma.sync path)
#define BK     32                // K per tile (halves)
#define SROW   40                // smem row stride in halves (80B; ldmatrix conflict-free)
#define STG    (256 * SROW)      // halves per stage (A:128 rows + B:128 rows)
#define NSTAGE 4

// ---------------------------------------------------------------------------
// Device scratch
// ---------------------------------------------------------------------------
__device__ float         g_Wdense[T_TOK * E_NUM];
__device__ unsigned char g_Slot[T_TOK * E_NUM];
__device__ int           g_counts[E_NUM];
__device__ int           g_tile_e[NT_MAX];
__device__ int           g_rtok[ROWS_MAX];
__device__ float         g_rw[ROWS_MAX];
__device__ unsigned char g_rslot[ROWS_MAX];

// fp16-preconverted operands
__device__ __half g_Xh[(size_t)T_TOK * H_DIM];
__device__ __half g_W1h[(size_t)E_NUM * I_DIM * H_DIM];
__device__ __half g_W3h[(size_t)E_NUM * I_DIM * H_DIM];
__device__ __half g_W2h[(size_t)E_NUM * H_DIM * I_DIM];
__device__ __half g_SW1h[(size_t)IS_DIM * H_DIM];
__device__ __half g_SW3h[(size_t)IS_DIM * H_DIM];
__device__ __half g_SW2h[(size_t)H_DIM * IS_DIM];

__device__ __half g_Hbh[(size_t)ROWS_MAX * I_DIM];   // routed intermediate
__device__ __half g_Hsh[(size_t)T_TOK * IS_DIM];     // shared intermediate
__device__ float  g_Y[(size_t)T_TOK * TOPK * H_DIM]; // per-slot routed outputs

// ---------------------------------------------------------------------------
// Helpers
// ---------------------------------------------------------------------------
__device__ __forceinline__ void mma_f16(float* c, const unsigned* a, const unsigned* b) {
    asm volatile(
        "mma.sync.aligned.m16n8k16.row.col.f32.f16.f16.f32 "
        "{%0,%1,%2,%3}, {%4,%5,%6,%7}, {%8,%9}, {%0,%1,%2,%3};\n"
        : "+f"(c[0]), "+f"(c[1]), "+f"(c[2]), "+f"(c[3])
        : "r"(a[0]), "r"(a[1]), "r"(a[2]), "r"(a[3]), "r"(b[0]), "r"(b[1]));
}

__device__ __forceinline__ void ldsm4(unsigned* r, const void* p) {
    unsigned a = (unsigned)__cvta_generic_to_shared(p);
    asm volatile("ldmatrix.sync.aligned.m8n8.x4.shared.b16 {%0,%1,%2,%3}, [%4];\n"
                 : "=r"(r[0]), "=r"(r[1]), "=r"(r[2]), "=r"(r[3]) : "r"(a));
}

__device__ __forceinline__ void cp16(void* sptr, const void* gptr) {
    unsigned sa = (unsigned)__cvta_generic_to_shared(sptr);
    asm volatile("cp.async.cg.shared.global [%0], [%1], 16;\n" :: "r"(sa), "l"(gptr));
}
#define CP_COMMIT() asm volatile("cp.async.commit_group;\n")
#define CP_WAIT2()  asm volatile("cp.async.wait_group 2;\n")

__device__ __forceinline__ float silu_f(float x) { return x / (1.f + __expf(-x)); }

// ---------------------------------------------------------------------------
// merged fp32->fp16 conversion for ALL operands (one launch) + counts clear
// ---------------------------------------------------------------------------
#define N8_X   (T_TOK * H_DIM / 8)
#define N8_W   (E_NUM * I_DIM * H_DIM / 8)
#define N8_SW  (IS_DIM * H_DIM / 8)
#define N8_TOT (N8_X + 3 * N8_W + 3 * N8_SW)

__device__ __forceinline__ void cv8(const float4* in, uint4* out, int i) {
    float4 v0 = in[2 * i];
    float4 v1 = in[2 * i + 1];
    __half2 h[4];
    h[0] = __floats2half2_rn(v0.x, v0.y);
    h[1] = __floats2half2_rn(v0.z, v0.w);
    h[2] = __floats2half2_rn(v1.x, v1.y);
    h[3] = __floats2half2_rn(v1.z, v1.w);
    out[i] = *reinterpret_cast<uint4*>(h);
}

__global__ void k_cvtall(const float4* __restrict__ x,
                         const float4* __restrict__ w1, const float4* __restrict__ w3,
                         const float4* __restrict__ w2, const float4* __restrict__ sw1,
                         const float4* __restrict__ sw3, const float4* __restrict__ sw2) {
    int i = blockIdx.x * blockDim.x + threadIdx.x;
    if (i < E_NUM) g_counts[i] = 0;
    if (i >= N8_TOT) return;
    if (i < N8_X) { cv8(x, (uint4*)g_Xh, i); return; }
    i -= N8_X;
    if (i < N8_W) { cv8(w1, (uint4*)g_W1h, i); return; }
    i -= N8_W;
    if (i < N8_W) { cv8(w3, (uint4*)g_W3h, i); return; }
    i -= N8_W;
    if (i < N8_W) { cv8(w2, (uint4*)g_W2h, i); return; }
    i -= N8_W;
    if (i < N8_SW) { cv8(sw1, (uint4*)g_SW1h, i); return; }
    i -= N8_SW;
    if (i < N8_SW) { cv8(sw3, (uint4*)g_SW3h, i); return; }
    i -= N8_SW;
    cv8(sw2, (uint4*)g_SW2h, i);
}

// ---------------------------------------------------------------------------
// 1) router (one warp per token) — writes full dense rows
// ---------------------------------------------------------------------------
__global__ void __launch_bounds__(128) k_router(const float* __restrict__ X,
                                                const float* __restrict__ GW,
                                                const float* __restrict__ EB) {
    const int warp = threadIdx.x >> 5;
    const int lane = threadIdx.x & 31;
    const int t = blockIdx.x * 4 + warp;

    __shared__ float ssw[4][32];
    __shared__ float ssc[4][32];
    __shared__ float sout[4][32];
    __shared__ unsigned char sslot[4][32];

    const float* x = X + (size_t)t * H_DIM;
    const float* g = GW + (size_t)lane * H_DIM;
    float a0=0.f,a1=0.f,a2=0.f,a3=0.f,a4=0.f,a5=0.f,a6=0.f,a7=0.f;
    for (int k = 0; k < H_DIM; k += 8) {
        float4 xv0 = *(const float4*)(x + k);
        float4 gv0 = *(const float4*)(g + k);
        float4 xv1 = *(const float4*)(x + k + 4);
        float4 gv1 = *(const float4*)(g + k + 4);
        a0 += xv0.x * gv0.x;  a1 += xv0.y * gv0.y;
        a2 += xv0.z * gv0.z;  a3 += xv0.w * gv0.w;
        a4 += xv1.x * gv1.x;  a5 += xv1.y * gv1.y;
        a6 += xv1.z * gv1.z;  a7 += xv1.w * gv1.w;
    }
    float logit = ((a0 + a4) + (a1 + a5)) + ((a2 + a6) + (a3 + a7));

    double scd = 1.0 / (1.0 + exp(-(double)logit));
    float sc = (float)scd;
    float sw = sc + EB[lane];
    ssw[warp][lane] = sw;
    ssc[warp][lane] = sc;
    sout[warp][lane] = 0.f;
    sslot[warp][lane] = 0;
    __syncwarp();

    if (lane == 0) {
        const float* swp = ssw[warp];
        const float* scp = ssc[warp];
        float gsc[NGRP];
#pragma unroll
        for (int gg = 0; gg < NGRP; gg++) {
            float m1 = -1e30f, m2 = -1e30f;
#pragma unroll
            for (int j = 0; j < 4; j++) {
                float v = swp[gg * 4 + j];
                if (v > m1) { m2 = m1; m1 = v; }
                else if (v > m2) m2 = v;
            }
            gsc[gg] = m1 + m2;
        }
        unsigned gmask = 0;
        for (int it = 0; it < TOPKG; it++) {
            int bg = 0; float bv = -1e30f;
            for (int gg = 0; gg < NGRP; gg++)
                if (!((gmask >> gg) & 1) && gsc[gg] > bv) { bv = gsc[gg]; bg = gg; }
            gmask |= 1u << bg;
        }
        int idx[TOPK]; float wsel[TOPK]; float wsum = 0.f;
        unsigned taken = 0;
        for (int it = 0; it < TOPK; it++) {
            int be = 0; float bv = -1e30f;
            for (int ee = 0; ee < E_NUM; ee++) {
                if (!((gmask >> (ee >> 2)) & 1)) continue;
                if ((taken >> ee) & 1) continue;
                if (swp[ee] > bv) { bv = swp[ee]; be = ee; }
            }
            taken |= 1u << be;
            idx[it] = be;
            wsel[it] = scp[be];
            wsum += scp[be];
        }
        float inv = 2.5f / (wsum + 1e-20f);
        for (int it = 0; it < TOPK; it++) {
            int ee = idx[it];
            sout[warp][ee] = wsel[it] * inv;
            sslot[warp][ee] = (unsigned char)it;
            atomicAdd(&g_counts[ee], 1);
        }
    }
    __syncwarp();
    g_Wdense[(size_t)t * E_NUM + lane] = sout[warp][lane];
    g_Slot[(size_t)t * E_NUM + lane]   = sslot[warp][lane];
}

// ---------------------------------------------------------------------------
// 2) scatter (folds offsets/tile-map/pad-init): one block per expert
// ---------------------------------------------------------------------------
__global__ void __launch_bounds__(1024) k_scatter() {
    const int e = blockIdx.x;
    const int tid = threadIdx.x;

    __shared__ int soff[E_NUM], spad[E_NUM];
    if (tid < 32) {
        int c = g_counts[tid];
        int p = (c + 127) & ~127;
        int incl = p;
#pragma unroll
        for (int d = 1; d < 32; d <<= 1) {
            int v = __shfl_up_sync(0xFFFFFFFFu, incl, d);
            if (tid >= d) incl += v;
        }
        soff[tid] = incl - p;
        spad[tid] = p;
    }
    __syncthreads();

    if (e == 0) {
        for (int tt = tid; tt < NT_MAX; tt += blockDim.x) {
            int owner = -1;
            int r = tt << 7;
#pragma unroll
            for (int ee = 0; ee < E_NUM; ee++)
                if (r >= soff[ee] && r < soff[ee] + spad[ee]) owner = ee;
            g_tile_e[tt] = owner;
        }
    }
    {
        int base = soff[e] + g_counts[e];
        int end  = soff[e] + spad[e];
        for (int i = base + tid; i < end; i += blockDim.x) {
            g_rtok[i] = -1;
            g_rw[i] = 0.f;
            g_rslot[i] = 0;
        }
    }

    const int base_t = tid * 4;
    float w[4]; int cnt = 0;
#pragma unroll
    for (int i = 0; i < 4; i++) {
        w[i] = g_Wdense[(size_t)(base_t + i) * E_NUM + e];
        cnt += (w[i] != 0.f);
    }
    const int lane = tid & 31, wid = tid >> 5;
    int incl = cnt;
#pragma unroll
    for (int d = 1; d < 32; d <<= 1) {
        int v = __shfl_up_sync(0xFFFFFFFFu, incl, d);
        if (lane >= d) incl += v;
    }
    __shared__ int wsum[32];
    if (lane == 31) wsum[wid] = incl;
    __syncthreads();
    if (wid == 0) {
        int v = wsum[lane];
#pragma unroll
        for (int d = 1; d < 32; d <<= 1) {
            int u = __shfl_up_sync(0xFFFFFFFFu, v, d);
            if (lane >= d) v += u;
        }
        wsum[lane] = v;
    }
    __syncthreads();
    int excl = incl - cnt + (wid ? wsum[wid - 1] : 0);
    int pos = soff[e] + excl;
#pragma unroll
    for (int i = 0; i < 4; i++) {
        if (w[i] != 0.f) {
            g_rtok[pos] = base_t + i;
            g_rw[pos] = w[i];
            g_rslot[pos] = g_Slot[(size_t)(base_t + i) * E_NUM + e];
            pos++;
        }
    }
}

// ---------------------------------------------------------------------------
// 4) up GEMM (fp16): H = silu(A W1^T) * (A W3^T).
//    CTA 128x128 with W1/W3 ROW-INTERLEAVED B tile (even smem rows = W1,
//    odd = W3): c-fragment adjacent columns (c0,c1) = (gate, up) pair, so
//    silu(c0)*c1 is computed in-register. 4 warps (2m x 2n), warp 64x64,
//    128 threads, 4-stage cp.async, 2 CTAs/SM. Produces 64 h-columns/CTA.
// ---------------------------------------------------------------------------
__global__ void __launch_bounds__(128, 2) k_up(const __half* __restrict__ W1b,
                                               const __half* __restrict__ W3b,
                                               int K, int N, int routed) {
    extern __shared__ __half smh[];
    const int bx = blockIdx.x, by = blockIdx.y;
    int e = 0;
    if (routed) { e = g_tile_e[by]; if (e < 0) return; }
    const size_t wstride = (size_t)N * K;
    const __half* W1 = W1b + (size_t)e * wstride;
    const __half* W3 = W3b + (size_t)e * wstride;
    __half* Hout = routed ? g_Hbh : g_Hsh;

    const int tid = threadIdx.x;
    const int lane = tid & 31;
    const int warp = tid >> 5;
    const int wm = (warp >> 1) << 6;   // 0,64
    const int wn = (warp & 1) << 6;    // 0,64 (B-row space)

    // A: 512 cp16 chunks (4/thread)
    const __half* apg[4]; int sAo[4];
#pragma unroll
    for (int i = 0; i < 4; i++) {
        int c = tid + 128 * i;
        int r = c >> 2, colh = (c & 3) << 3;
        int grow = (by << 7) + r;
        int tok = routed ? g_rtok[grow] : grow;
        if (tok < 0) tok = 0;
        apg[i] = g_Xh + (size_t)tok * K + colh;
        sAo[i] = r * SROW + colh;
    }
    // B: W1 -> even rows, W3 -> odd rows (2 chunks each per thread)
    const __half *b1g[2], *b3g[2]; int sB1o[2], sB3o[2];
#pragma unroll
    for (int i = 0; i < 2; i++) {
        int c = tid + 128 * i;
        int r = c >> 2, colh = (c & 3) << 3;
        b1g[i] = W1 + (size_t)((bx << 6) + r) * K + colh;
        b3g[i] = W3 + (size_t)((bx << 6) + r) * K + colh;
        sB1o[i] = (128 + 2 * r) * SROW + colh;
        sB3o[i] = (128 + 2 * r + 1) * SROW + colh;
    }

    float cc[4][8][4];
#pragma unroll
    for (int mi = 0; mi < 4; mi++)
#pragma unroll
        for (int ni = 0; ni < 8; ni++)
#pragma unroll
            for (int q = 0; q < 4; q++) cc[mi][ni][q] = 0.f;

    const int NT = K >> 5;

#define UP_FETCH(KT) do {                                         \
        __half* s_ = smh + ((KT) % NSTAGE) * STG;                 \
        int off_ = (KT) << 5;                                     \
        cp16(s_ + sAo[0], apg[0] + off_);                         \
        cp16(s_ + sAo[1], apg[1] + off_);                         \
        cp16(s_ + sAo[2], apg[2] + off_);                         \
        cp16(s_ + sAo[3], apg[3] + off_);                         \
        cp16(s_ + sB1o[0], b1g[0] + off_);                        \
        cp16(s_ + sB1o[1], b1g[1] + off_);                        \
        cp16(s_ + sB3o[0], b3g[0] + off_);                        \
        cp16(s_ + sB3o[1], b3g[1] + off_);                        \
    } while (0)

    UP_FETCH(0); CP_COMMIT();
    UP_FETCH(1); CP_COMMIT();
    UP_FETCH(2); CP_COMMIT();

    for (int kt = 0; kt < NT; kt++) {
        CP_WAIT2();
        __syncthreads();
        if (kt + 3 < NT) UP_FETCH(kt + 3);
        CP_COMMIT();

        const __half* As = smh + (kt % NSTAGE) * STG;
        const __half* Bs = As + 128 * SROW;

        unsigned a[2][4][4], b[2][8][2];
#pragma unroll
        for (int kk = 0; kk < 2; kk++) {
            const int kb = kk << 4;
            {
                const __half* p = As + (size_t)(wm + (lane & 15)) * SROW
                                   + kb + ((lane >> 4) << 3);
#pragma unroll
                for (int mi = 0; mi < 4; mi++)
                    ldsm4(a[kk][mi], p + mi * 16 * SROW);
            }
            {
                int row = ((lane >> 4) << 3) + (lane & 7);
                int col = kb + (((lane >> 3) & 1) << 3);
#pragma unroll
                for (int g2 = 0; g2 < 4; g2++) {
                    unsigned t0[4];
                    const __half* p = Bs + (size_t)(wn + g2 * 16 + row) * SROW + col;
                    ldsm4(t0, p);
                    b[kk][2 * g2][0]     = t0[0]; b[kk][2 * g2][1]     = t0[1];
                    b[kk][2 * g2 + 1][0] = t0[2]; b[kk][2 * g2 + 1][1] = t0[3];
                }
            }
        }
#pragma unroll
        for (int kk = 0; kk < 2; kk++)
#pragma unroll
            for (int mi = 0; mi < 4; mi++)
#pragma unroll
                for (int ni = 0; ni < 8; ni++)
                    mma_f16(cc[mi][ni], a[kk][mi], b[kk][ni]);
    }
#undef UP_FETCH

    // epilogue: (c0,c1)=(g,u) at h-col, (c2,c3)=(g,u) at row+8
    const int lr = lane >> 2, lq = lane & 3;
#pragma unroll
    for (int mi = 0; mi < 4; mi++)
#pragma unroll
        for (int ni = 0; ni < 8; ni++) {
            int hcol = (bx << 6) + ((warp & 1) << 5) + ni * 4 + lq;
            int row0 = (by << 7) + wm + mi * 16 + lr;
            float h0 = silu_f(cc[mi][ni][0]) * cc[mi][ni][1];
            float h1 = silu_f(cc[mi][ni][2]) * cc[mi][ni][3];
            Hout[(size_t)row0 * N + hcol]       = __float2half(h0);
            Hout[(size_t)(row0 + 8) * N + hcol] = __float2half(h1);
        }
}

// ---------------------------------------------------------------------------
// 5) down GEMM (fp16): Y = H W2^T. CTA 128x128, 4 warps (2m x 2n),
//    warp 64x64, 128 threads, 4-stage cp.async, 2 CTAs/SM.
// ---------------------------------------------------------------------------
__global__ void __launch_bounds__(128, 2) k_down(const __half* __restrict__ W2b,
                                                 int K, int routed,
                                                 float* __restrict__ Outp) {
    extern __shared__ __half smh[];
    const int bx = blockIdx.x, by = blockIdx.y;
    const int N = H_DIM;
    int e = 0;
    if (routed) { e = g_tile_e[by]; if (e < 0) return; }
    const __half* W2 = W2b + (size_t)e * N * K;
    const __half* Ain = routed ? g_Hbh : g_Hsh;

    const int tid = threadIdx.x;
    const int lane = tid & 31;
    const int warp = tid >> 5;
    const int wm = (warp >> 1) << 6;   // 0,64
    const int wn = (warp & 1) << 6;    // 0,64

    const __half *apg[4], *bpg[4]; int sLo[4];
#pragma unroll
    for (int i = 0; i < 4; i++) {
        int c = tid + 128 * i;
        int r = c >> 2, colh = (c & 3) << 3;
        apg[i] = Ain + (size_t)((by << 7) + r) * K + colh;
        bpg[i] = W2 + (size_t)((bx << 7) + r) * K + colh;
        sLo[i] = r * SROW + colh;
    }

    float cc[4][8][4];
#pragma unroll
    for (int mi = 0; mi < 4; mi++)
#pragma unroll
        for (int ni = 0; ni < 8; ni++)
#pragma unroll
            for (int q = 0; q < 4; q++) cc[mi][ni][q] = 0.f;

    const int NT = K >> 5;

#define DN_FETCH(KT) do {                                         \
        __half* s_ = smh + ((KT) % NSTAGE) * STG;                 \
        int off_ = (KT) << 5;                                     \
        cp16(s_ + sLo[0], apg[0] + off_);                         \
        cp16(s_ + sLo[1], apg[1] + off_);                         \
        cp16(s_ + sLo[2], apg[2] + off_);                         \
        cp16(s_ + sLo[3], apg[3] + off_);                         \
        cp16(s_ + 128 * SROW + sLo[0], bpg[0] + off_);            \
        cp16(s_ + 128 * SROW + sLo[1], bpg[1] + off_);            \
        cp16(s_ + 128 * SROW + sLo[2], bpg[2] + off_);            \
        cp16(s_ + 128 * SROW + sLo[3], bpg[3] + off_);            \
    } while (0)

    DN_FETCH(0); CP_COMMIT();
    DN_FETCH(1); CP_COMMIT();
    DN_FETCH(2); CP_COMMIT();

    for (int kt = 0; kt < NT; kt++) {
        CP_WAIT2();
        __syncthreads();
        if (kt + 3 < NT) DN_FETCH(kt + 3);
        CP_COMMIT();

        const __half* As = smh + (kt % NSTAGE) * STG;
        const __half* Bs = As + 128 * SROW;

        unsigned a[2][4][4], b[2][8][2];
#pragma unroll
        for (int kk = 0; kk < 2; kk++) {
            const int kb = kk << 4;
            {
                const __half* p = As + (size_t)(wm + (lane & 15)) * SROW
                                   + kb + ((lane >> 4) << 3);
#pragma unroll
                for (int mi = 0; mi < 4; mi++)
                    ldsm4(a[kk][mi], p + mi * 16 * SROW);
            }
            {
                int row = ((lane >> 4) << 3) + (lane & 7);
                int col = kb + (((lane >> 3) & 1) << 3);
#pragma unroll
                for (int g2 = 0; g2 < 4; g2++) {
                    unsigned t0[4];
                    const __half* p = Bs + (size_t)(wn + g2 * 16 + row) * SROW + col;
                    ldsm4(t0, p);
                    b[kk][2 * g2][0]     = t0[0]; b[kk][2 * g2][1]     = t0[1];
                    b[kk][2 * g2 + 1][0] = t0[2]; b[kk][2 * g2 + 1][1] = t0[3];
                }
            }
        }
#pragma unroll
        for (int kk = 0; kk < 2; kk++)
#pragma unroll
            for (int mi = 0; mi < 4; mi++)
#pragma unroll
                for (int ni = 0; ni < 8; ni++)
                    mma_f16(cc[mi][ni], a[kk][mi], b[kk][ni]);
    }
#undef DN_FETCH

    const int lr = lane >> 2, lc2 = (lane & 3) << 1;
#pragma unroll
    for (int mi = 0; mi < 4; mi++)
#pragma unroll
        for (int h = 0; h < 2; h++) {
            int row = (by << 7) + wm + mi * 16 + lr + h * 8;
            if (routed) {
                int tok = g_rtok[row];
                if (tok < 0) continue;
                float w = g_rw[row];
                int slot = g_rslot[row];
                float* yrow = &g_Y[((size_t)tok * TOPK + slot) * H_DIM];
#pragma unroll
                for (int ni = 0; ni < 8; ni++) {
                    int col = (bx << 7) + wn + ni * 8 + lc2;
                    float2 v;
                    v.x = w * cc[mi][ni][h * 2];
                    v.y = w * cc[mi][ni][h * 2 + 1];
                    *reinterpret_cast<float2*>(&yrow[col]) = v;
                }
            } else {
                float* orow = &Outp[(size_t)row * H_DIM];
#pragma unroll
                for (int ni = 0; ni < 8; ni++) {
                    int col = (bx << 7) + wn + ni * 8 + lc2;
                    float2 v;
                    v.x = cc[mi][ni][h * 2];
                    v.y = cc[mi][ni][h * 2 + 1];
                    *reinterpret_cast<float2*>(&orow[col]) = v;
                }
            }
        }
}

// ---------------------------------------------------------------------------
// 6) combine: out += sum over 8 routed slots
// ---------------------------------------------------------------------------
__global__ void k_combine(float* __restrict__ out) {
    int i = blockIdx.x * blockDim.x + threadIdx.x;
    const float4* Y4 = reinterpret_cast<const float4*>(g_Y);
    float4* O4 = reinterpret_cast<float4*>(out);
    int t = i >> 9;
    int c = i & 511;
    float4 acc = O4[i];
    const float4* yb = Y4 + ((size_t)t * TOPK) * 512 + c;
#pragma unroll
    for (int s = 0; s < TOPK; s++) {
        float4 v = yb[(size_t)s * 512];
        acc.x += v.x; acc.y += v.y; acc.z += v.z; acc.w += v.w;
    }
    O4[i] = acc;
}

// ---------------------------------------------------------------------------
// Launch
// ---------------------------------------------------------------------------
extern "C" void kernel_launch(void* const* d_in, const int* in_sizes, int n_in,
                              void* d_out, int out_size) {
    const float* hs  = (const float*)d_in[0];
    const float* gw  = (const float*)d_in[1];
    const float* eb  = (const float*)d_in[2];
    const float* w1  = (const float*)d_in[3];
    const float* w3  = (const float*)d_in[4];
    const float* w2  = (const float*)d_in[5];
    const float* sw1 = (const float*)d_in[6];
    const float* sw3 = (const float*)d_in[7];
    const float* sw2 = (const float*)d_in[8];
    float* out = (float*)d_out;

    static __half* p_W1h = nullptr;
    if (!p_W1h) {
        cudaGetSymbolAddress((void**)&p_W1h, g_W1h);
        cudaFuncSetAttribute((const void*)k_up,
                             cudaFuncAttributeMaxDynamicSharedMemorySize,
                             NSTAGE * STG * (int)sizeof(__half));
        cudaFuncSetAttribute((const void*)k_down,
                             cudaFuncAttributeMaxDynamicSharedMemorySize,
                             NSTAGE * STG * (int)sizeof(__half));
    }
    static __half *p_W3h = nullptr, *p_W2h = nullptr, *p_SW1h = nullptr,
                  *p_SW3h = nullptr, *p_SW2h = nullptr;
    if (!p_W3h) {
        cudaGetSymbolAddress((void**)&p_W3h,  g_W3h);
        cudaGetSymbolAddress((void**)&p_W2h,  g_W2h);
        cudaGetSymbolAddress((void**)&p_SW1h, g_SW1h);
        cudaGetSymbolAddress((void**)&p_SW3h, g_SW3h);
        cudaGetSymbolAddress((void**)&p_SW2h, g_SW2h);
    }

    // 0) merged fp32->fp16 conversion (also zeroes g_counts)
    k_cvtall<<<(N8_TOT + 255) / 256, 256>>>(
        (const float4*)hs, (const float4*)w1, (const float4*)w3, (const float4*)w2,
        (const float4*)sw1, (const float4*)sw3, (const float4*)sw2);

    // 1) routing
    k_router<<<T_TOK / 4, 128>>>(hs, gw, eb);
    k_scatter<<<E_NUM, 1024>>>();

    const int smem = NSTAGE * STG * (int)sizeof(__half);

    // routed experts (up: 64 h-cols per CTA -> grid.x = I_DIM/64)
    k_up<<<dim3(I_DIM / 64, NT_MAX), 128, smem>>>(p_W1h, p_W3h, H_DIM, I_DIM, 1);
    k_down<<<dim3(H_DIM / 128, NT_MAX), 128, smem>>>(p_W2h, I_DIM, 1, nullptr);

    // shared expert (writes d_out directly)
    k_up<<<dim3(IS_DIM / 64, T_TOK / 128), 128, smem>>>(p_SW1h, p_SW3h, H_DIM, IS_DIM, 0);
    k_down<<<dim3(H_DIM / 128, T_TOK / 128), 128, smem>>>(p_SW2h, IS_DIM, 0, out);

    // final combine
    k_combine<<<(T_TOK * H_DIM / 4) / 256, 256>>>(out);

    (void)in_sizes; (void)n_in; (void)out_size;
}